// round 12
// baseline (speedup 1.0000x reference)
#include <cuda_runtime.h>
#include <cstdint>

#define DD 128
#define ROWS_ITER 256        // rows per CTA iteration (16 per warp)
#define ITERS 4              // iterations per CTA -> 1024 rows/CTA
#define NTHREADS 512

// ---- smem byte offsets ----
#define SM_B1   0            // GEMM1 B: float4 {hi0,hi1,lo0,lo1} frag-packed (128KB)
#define SM_B2   131072       // GEMM2 B: float2 {b0,b1} tf32-hi frag-packed (64KB)
#define SM_ZI   196608       // indices: 256 rows x 132 bytes
#define SM_SCL  230400       // 128 f32
#define SM_ISCL 230912       // 128 f32
#define SMEM_BYTES 231424

__device__ __forceinline__ uint32_t tf32u(float x) {
    uint32_t r;
    asm("cvt.rna.tf32.f32 %0, %1;" : "=r"(r) : "f"(x));
    return r;
}
__device__ __forceinline__ float tf32f(float x) { return __uint_as_float(tf32u(x)); }

__device__ __forceinline__ void mma8(float d[4], const uint32_t a[4],
                                     uint32_t b0, uint32_t b1) {
    asm volatile(
        "mma.sync.aligned.m16n8k8.row.col.f32.tf32.tf32.f32 "
        "{%0,%1,%2,%3}, {%4,%5,%6,%7}, {%8,%9}, {%0,%1,%2,%3};"
        : "+f"(d[0]), "+f"(d[1]), "+f"(d[2]), "+f"(d[3])
        : "r"(a[0]), "r"(a[1]), "r"(a[2]), "r"(a[3]), "r"(b0), "r"(b1));
}

__device__ __forceinline__ void split4(const float f[4], uint32_t h[4], uint32_t l[4]) {
    #pragma unroll
    for (int i = 0; i < 4; ++i) {
        h[i] = tf32u(f[i]);
        l[i] = tf32u(f[i] - __uint_as_float(h[i]));
    }
}

extern "C" __global__ void __launch_bounds__(NTHREADS, 1)
rotadapt_mma_kernel(const float* __restrict__ k,
                    const float* __restrict__ rot,
                    const float* __restrict__ scales,
                    const float* __restrict__ cent,
                    float* __restrict__ out)
{
    extern __shared__ char sb[];
    float* sclp  = (float*)(sb + SM_SCL);
    float* isclp = (float*)(sb + SM_ISCL);

    const int tid  = threadIdx.x;
    const int lane = tid & 31, w = tid >> 5;      // 16 warps
    const int g = lane >> 2, t = lane & 3;
    const int rA = 16 * w + g;                    // warp owns rows [16w, 16w+16)

    // ---- prologue: build both fragment tables directly ----
    // B1[u=(ks*16+nt)*32+lane] = {Rh[n][kk], Rh[n][kk+4], Rl[n][kk], Rl[n][kk+4]}
    //   n = 8*nt + g', kk = 8*ks + t'   (GEMM1: B[kk][n] = R[n][kk])
    // B2[u] = {tf32(R[kk][n]), tf32(R[kk+4][n])}          (GEMM2: B[kk][n] = R[kk][n])
    for (int u = tid; u < 16 * 16 * 32; u += NTHREADS) {
        int ln = u & 31, nt = (u >> 5) & 15, ks = u >> 9;
        int gg = ln >> 2, t2 = ln & 3;
        int n  = 8 * nt + gg;
        int kk = 8 * ks + t2;
        float v0 = rot[n * DD + kk], v1 = rot[n * DD + kk + 4];
        float h0 = tf32f(v0), h1 = tf32f(v1);
        ((float4*)(sb + SM_B1))[u] = make_float4(h0, h1, tf32f(v0 - h0), tf32f(v1 - h1));
        float w0 = rot[kk * DD + n], w1 = rot[(kk + 4) * DD + n];
        ((float2*)(sb + SM_B2))[u] = make_float2(tf32f(w0), tf32f(w1));
    }
    if (tid < DD) {
        float s = scales[tid];
        sclp[tid]  = s;
        isclp[tid] = 1.0f / fmaxf(s, 1e-6f);
    }

    float bn[7];
    #pragma unroll
    for (int q = 0; q < 7; ++q) bn[q] = 0.5f * (cent[q] + cent[q + 1]);
    const float ccv = cent[lane & 7];

    __syncthreads();   // the ONLY block barrier: B tables + scales ready

    const float4* bq  = (const float4*)(sb + SM_B1);
    const float2* b2q = (const float2*)(sb + SM_B2);
    char* zi = sb + SM_ZI;

    const long ctabase = (long)blockIdx.x * (ROWS_ITER * ITERS);

    for (int tt = 0; tt < ITERS; ++tt) {
        const long rowbase = ctabase + (long)tt * ROWS_ITER;

        // ---- GEMM1 (3-pass tf32) on RAW k: acc = k @ R^T (unnormalized) ----
        float acc[16][4];
        #pragma unroll
        for (int nt = 0; nt < 16; ++nt)
            #pragma unroll
            for (int p = 0; p < 4; ++p) acc[nt][p] = 0.0f;

        {
            const float* k0 = k + (rowbase + rA) * (long)DD;
            const float* k1 = k0 + 8 * DD;

            #pragma unroll 2
            for (int ks = 0; ks < 16; ++ks) {
                int o = 8 * ks + t;
                float fA[4] = { k0[o], k1[o], k0[o + 4], k1[o + 4] };
                uint32_t ah[4], al[4];
                split4(fA, ah, al);

                float4 bb[2][4];
                #pragma unroll
                for (int j = 0; j < 4; ++j)
                    bb[0][j] = bq[(ks * 16 + j) * 32 + lane];
                #pragma unroll
                for (int grp = 0; grp < 4; ++grp) {
                    const int cur = grp & 1, nxt = cur ^ 1;
                    if (grp < 3) {
                        #pragma unroll
                        for (int j = 0; j < 4; ++j)
                            bb[nxt][j] = bq[(ks * 16 + (grp + 1) * 4 + j) * 32 + lane];
                    }
                    #pragma unroll
                    for (int j = 0; j < 4; ++j) {
                        int nt = grp * 4 + j;
                        uint32_t bh0 = __float_as_uint(bb[cur][j].x);
                        uint32_t bh1 = __float_as_uint(bb[cur][j].y);
                        uint32_t bl0 = __float_as_uint(bb[cur][j].z);
                        uint32_t bl1 = __float_as_uint(bb[cur][j].w);
                        mma8(acc[nt], ah, bh0, bh1);
                        mma8(acc[nt], al, bh0, bh1);
                        mma8(acc[nt], ah, bl0, bl1);
                    }
                }
            }
        }

        // ---- norms from acc: R orthogonal => ||k @ R^T|| = ||k|| ----
        float nrm0, nrm1, inv0, inv1;
        {
            float ssq0 = 0.0f, ssq1 = 0.0f;
            #pragma unroll
            for (int nt = 0; nt < 16; ++nt) {
                ssq0 += acc[nt][0] * acc[nt][0] + acc[nt][1] * acc[nt][1];
                ssq1 += acc[nt][2] * acc[nt][2] + acc[nt][3] * acc[nt][3];
            }
            ssq0 += __shfl_xor_sync(0xffffffffu, ssq0, 1);
            ssq0 += __shfl_xor_sync(0xffffffffu, ssq0, 2);
            ssq1 += __shfl_xor_sync(0xffffffffu, ssq1, 1);
            ssq1 += __shfl_xor_sync(0xffffffffu, ssq1, 2);
            nrm0 = sqrtf(ssq0);
            nrm1 = sqrtf(ssq1);
            inv0 = 1.0f / (nrm0 + 1e-10f);
            inv1 = 1.0f / (nrm1 + 1e-10f);
        }

        // ---- prefetch next iteration's k toward L2 ----
        if (tt + 1 < ITERS) {
            const char* np = (const char*)(k + (rowbase + ROWS_ITER) * (long)DD);
            #pragma unroll
            for (int pf = 0; pf < 2; ++pf)
                asm volatile("prefetch.global.L2 [%0];"
                             :: "l"(np + (pf * NTHREADS + tid) * 128));
        }

        // ---- epilogue 1: scale*invnorm -> bucketize -> 8-bit indices to smem ----
        {
            const float2* scl2 = (const float2*)(sb + SM_SCL);
            #pragma unroll
            for (int nt = 0; nt < 16; ++nt) {
                float2 sc = scl2[(8 * nt + 2 * t) >> 1];
                float f0 = acc[nt][0] * sc.x * inv0, f1 = acc[nt][1] * sc.y * inv0;
                float f2 = acc[nt][2] * sc.x * inv1, f3 = acc[nt][3] * sc.y * inv1;
                int i0 = 0, i1 = 0, i2 = 0, i3 = 0;
                #pragma unroll
                for (int q = 0; q < 7; ++q) {
                    i0 += (f0 > bn[q]); i1 += (f1 > bn[q]);
                    i2 += (f2 > bn[q]); i3 += (f3 > bn[q]);
                }
                *(uint16_t*)(zi + rA * 132 + 8 * nt + 2 * t)       = (uint16_t)(i0 | (i1 << 8));
                *(uint16_t*)(zi + (rA + 8) * 132 + 8 * nt + 2 * t) = (uint16_t)(i2 | (i3 << 8));
            }
        }
        __syncwarp();

        // ---- GEMM2 (2-pass tf32): dedicated packed B table, reuse acc regs ----
        #pragma unroll
        for (int nt = 0; nt < 16; ++nt)
            #pragma unroll
            for (int p = 0; p < 4; ++p) acc[nt][p] = 0.0f;

        {
            #pragma unroll 2
            for (int ks = 0; ks < 16; ++ks) {
                float is0 = isclp[8 * ks + t], is1 = isclp[8 * ks + t + 4];
                int sh = 8 * t;
                uint32_t zh[4], zl[4];
                {
                    uint32_t wa = *(const uint32_t*)(zi + rA * 132 + 8 * ks);
                    uint32_t wb = *(const uint32_t*)(zi + rA * 132 + 8 * ks + 4);
                    uint32_t wc = *(const uint32_t*)(zi + (rA + 8) * 132 + 8 * ks);
                    uint32_t wd = *(const uint32_t*)(zi + (rA + 8) * 132 + 8 * ks + 4);
                    float fz[4] = {
                        __shfl_sync(0xffffffffu, ccv, (wa >> sh) & 0xff) * is0,
                        __shfl_sync(0xffffffffu, ccv, (wc >> sh) & 0xff) * is0,
                        __shfl_sync(0xffffffffu, ccv, (wb >> sh) & 0xff) * is1,
                        __shfl_sync(0xffffffffu, ccv, (wd >> sh) & 0xff) * is1 };
                    split4(fz, zh, zl);
                }

                float2 cb[2][4];
                #pragma unroll
                for (int j = 0; j < 4; ++j)
                    cb[0][j] = b2q[(ks * 16 + j) * 32 + lane];
                #pragma unroll
                for (int grp = 0; grp < 4; ++grp) {
                    const int cur = grp & 1, nxt = cur ^ 1;
                    if (grp < 3) {
                        #pragma unroll
                        for (int j = 0; j < 4; ++j)
                            cb[nxt][j] = b2q[(ks * 16 + (grp + 1) * 4 + j) * 32 + lane];
                    }
                    #pragma unroll
                    for (int j = 0; j < 4; ++j) {
                        int nt = grp * 4 + j;
                        uint32_t b0 = __float_as_uint(cb[cur][j].x);
                        uint32_t b1 = __float_as_uint(cb[cur][j].y);
                        mma8(acc[nt], zh, b0, b1);
                        mma8(acc[nt], zl, b0, b1);
                    }
                }
            }
        }

        // ---- epilogue 2: x norm, store ----
        {
            float* o0 = out + (rowbase + rA) * (long)DD;
            float* o1 = o0 + 8 * DD;
            #pragma unroll
            for (int nt = 0; nt < 16; ++nt) {
                int c = 8 * nt + 2 * t;
                *(float2*)(o0 + c) = make_float2(acc[nt][0] * nrm0, acc[nt][1] * nrm0);
                *(float2*)(o1 + c) = make_float2(acc[nt][2] * nrm1, acc[nt][3] * nrm1);
            }
        }
    }
}

extern "C" void kernel_launch(void* const* d_in, const int* in_sizes, int n_in,
                              void* d_out, int out_size) {
    const float* k      = (const float*)d_in[0];
    const float* rot    = (const float*)d_in[1];
    const float* scales = (const float*)d_in[2];
    const float* cent   = (const float*)d_in[3];
    float* out = (float*)d_out;

    int nrows = in_sizes[0] / DD;
    int nblocks = nrows / (ROWS_ITER * ITERS);   // 1048576 / 1024 = 1024

    cudaFuncSetAttribute(rotadapt_mma_kernel,
                         cudaFuncAttributeMaxDynamicSharedMemorySize, SMEM_BYTES);
    rotadapt_mma_kernel<<<nblocks, NTHREADS, SMEM_BYTES>>>(k, rot, scales, cent, out);
}

// round 13
// speedup vs baseline: 1.6373x; 1.6373x over previous
#include <cuda_runtime.h>
#include <cuda_fp16.h>
#include <cstdint>

#define DD 128
#define ROWS_ITER 256        // rows per CTA iteration (16 per warp)
#define ITERS 4              // iterations per CTA -> 1024 rows/CTA
#define NTHREADS 512

// ---- smem byte offsets ----
#define SM_B1   0            // GEMM1 B: uint4 {bh0,bh1,bl0,bl1} f16x2 frags (64KB)
#define SM_B2   65536        // GEMM2 B: uint2 {b0,b1} f16x2 hi frags (32KB)
#define SM_ZI   98304        // indices: 256 rows x 132 bytes
#define SM_SCL  132096       // 128 f32
#define SM_ISCL 132608       // 128 f32
#define SMEM_BYTES 133120

// D += A(f16) * B(f16), m16n8k16, fp32 accumulate
__device__ __forceinline__ void mma16(float d[4], const uint32_t a[4],
                                      uint32_t b0, uint32_t b1) {
    asm volatile(
        "mma.sync.aligned.m16n8k16.row.col.f32.f16.f16.f32 "
        "{%0,%1,%2,%3}, {%4,%5,%6,%7}, {%8,%9}, {%0,%1,%2,%3};"
        : "+f"(d[0]), "+f"(d[1]), "+f"(d[2]), "+f"(d[3])
        : "r"(a[0]), "r"(a[1]), "r"(a[2]), "r"(a[3]), "r"(b0), "r"(b1));
}

// pack two floats into f16x2 (a -> low half, b -> high half)
__device__ __forceinline__ uint32_t h2pack(float a, float b) {
    __half2 h = __floats2half2_rn(a, b);
    return *(uint32_t*)&h;
}
__device__ __forceinline__ float2 h2unpack(uint32_t u) {
    __half2 h = *(__half2*)&u;
    return __half22float2(h);
}

extern "C" __global__ void __launch_bounds__(NTHREADS, 1)
rotadapt_mma_kernel(const float* __restrict__ k,
                    const float* __restrict__ rot,
                    const float* __restrict__ scales,
                    const float* __restrict__ cent,
                    float* __restrict__ out)
{
    extern __shared__ char sb[];
    float* sclp  = (float*)(sb + SM_SCL);
    float* isclp = (float*)(sb + SM_ISCL);

    const int tid  = threadIdx.x;
    const int lane = tid & 31, w = tid >> 5;      // 16 warps
    const int g = lane >> 2, t = lane & 3;
    const int rA = 16 * w + g;                    // warp owns rows [16w, 16w+16)

    // ---- prologue: build f16 hi/lo fragment tables ----
    // u = (ks16*16 + nt)*32 + lane ; n = 8*nt + g', c = 16*ks16 + 2*t'
    // B1 (GEMM1, B[kk][n] = R[n][kk]):  bh0={Rh[n][c],Rh[n][c+1]}, bh1={..c+8,c+9}, bl*
    // B2 (GEMM2, B[kk][n] = R[kk][n]):  b0={Rh[c][n],Rh[c+1][n]},  b1={..c+8,c+9}
    for (int u = tid; u < 8 * 16 * 32; u += NTHREADS) {
        int ln = u & 31, nt = (u >> 5) & 15, ks = u >> 9;
        int gg = ln >> 2, t2 = ln & 3;
        int n = 8 * nt + gg;
        int c = 16 * ks + 2 * t2;
        float r0 = rot[n * DD + c],     r1 = rot[n * DD + c + 1];
        float r2 = rot[n * DD + c + 8], r3 = rot[n * DD + c + 9];
        uint32_t bh0 = h2pack(r0, r1);
        uint32_t bh1 = h2pack(r2, r3);
        float2 h01 = h2unpack(bh0);
        float2 h23 = h2unpack(bh1);
        uint32_t bl0 = h2pack(r0 - h01.x, r1 - h01.y);
        uint32_t bl1 = h2pack(r2 - h23.x, r3 - h23.y);
        ((uint4*)(sb + SM_B1))[u] = make_uint4(bh0, bh1, bl0, bl1);
        uint32_t c0p = h2pack(rot[c * DD + n], rot[(c + 1) * DD + n]);
        uint32_t c1p = h2pack(rot[(c + 8) * DD + n], rot[(c + 9) * DD + n]);
        ((uint2*)(sb + SM_B2))[u] = make_uint2(c0p, c1p);
    }
    if (tid < DD) {
        float s = scales[tid];
        sclp[tid]  = s;
        isclp[tid] = 1.0f / fmaxf(s, 1e-6f);
    }

    float bn[7];
    #pragma unroll
    for (int q = 0; q < 7; ++q) bn[q] = 0.5f * (cent[q] + cent[q + 1]);
    const float ccv = cent[lane & 7];

    __syncthreads();   // the ONLY block barrier: B tables + scales ready

    const uint4* b1q = (const uint4*)(sb + SM_B1);
    const uint2* b2q = (const uint2*)(sb + SM_B2);
    char* zi = sb + SM_ZI;

    const long ctabase = (long)blockIdx.x * (ROWS_ITER * ITERS);

    for (int tt = 0; tt < ITERS; ++tt) {
        const long rowbase = ctabase + (long)tt * ROWS_ITER;

        // ---- GEMM1 (hi/lo fp16, 3 MMAs per k16 step) on RAW k ----
        float acc[16][4];
        #pragma unroll
        for (int nt = 0; nt < 16; ++nt)
            #pragma unroll
            for (int p = 0; p < 4; ++p) acc[nt][p] = 0.0f;

        {
            const float* k0 = k + (rowbase + rA) * (long)DD;
            const float* k1 = k0 + 8 * DD;

            #pragma unroll 2
            for (int ks = 0; ks < 8; ++ks) {
                int c0 = 16 * ks + 2 * t;
                float2 v00 = *(const float2*)&k0[c0];
                float2 v10 = *(const float2*)&k1[c0];
                float2 v08 = *(const float2*)&k0[c0 + 8];
                float2 v18 = *(const float2*)&k1[c0 + 8];
                uint32_t ah[4], al[4];
                ah[0] = h2pack(v00.x, v00.y);
                ah[1] = h2pack(v10.x, v10.y);
                ah[2] = h2pack(v08.x, v08.y);
                ah[3] = h2pack(v18.x, v18.y);
                float2 h0 = h2unpack(ah[0]), h1 = h2unpack(ah[1]);
                float2 h2 = h2unpack(ah[2]), h3 = h2unpack(ah[3]);
                al[0] = h2pack(v00.x - h0.x, v00.y - h0.y);
                al[1] = h2pack(v10.x - h1.x, v10.y - h1.y);
                al[2] = h2pack(v08.x - h2.x, v08.y - h2.y);
                al[3] = h2pack(v18.x - h3.x, v18.y - h3.y);

                uint4 bb[2][4];
                #pragma unroll
                for (int j = 0; j < 4; ++j)
                    bb[0][j] = b1q[(ks * 16 + j) * 32 + lane];
                #pragma unroll
                for (int grp = 0; grp < 4; ++grp) {
                    const int cur = grp & 1, nxt = cur ^ 1;
                    if (grp < 3) {
                        #pragma unroll
                        for (int j = 0; j < 4; ++j)
                            bb[nxt][j] = b1q[(ks * 16 + (grp + 1) * 4 + j) * 32 + lane];
                    }
                    #pragma unroll
                    for (int j = 0; j < 4; ++j) {
                        int nt = grp * 4 + j;
                        mma16(acc[nt], ah, bb[cur][j].x, bb[cur][j].y);   // hi*hi
                        mma16(acc[nt], al, bb[cur][j].x, bb[cur][j].y);   // lo*hi
                        mma16(acc[nt], ah, bb[cur][j].z, bb[cur][j].w);   // hi*lo
                    }
                }
            }
        }

        // ---- norms from acc: R orthogonal => ||k @ R^T|| = ||k|| ----
        float nrm0, nrm1, inv0, inv1;
        {
            float ssq0 = 0.0f, ssq1 = 0.0f;
            #pragma unroll
            for (int nt = 0; nt < 16; ++nt) {
                ssq0 += acc[nt][0] * acc[nt][0] + acc[nt][1] * acc[nt][1];
                ssq1 += acc[nt][2] * acc[nt][2] + acc[nt][3] * acc[nt][3];
            }
            ssq0 += __shfl_xor_sync(0xffffffffu, ssq0, 1);
            ssq0 += __shfl_xor_sync(0xffffffffu, ssq0, 2);
            ssq1 += __shfl_xor_sync(0xffffffffu, ssq1, 1);
            ssq1 += __shfl_xor_sync(0xffffffffu, ssq1, 2);
            nrm0 = sqrtf(ssq0);
            nrm1 = sqrtf(ssq1);
            inv0 = 1.0f / (nrm0 + 1e-10f);
            inv1 = 1.0f / (nrm1 + 1e-10f);
        }

        // ---- prefetch next iteration's k toward L2 ----
        if (tt + 1 < ITERS) {
            const char* np = (const char*)(k + (rowbase + ROWS_ITER) * (long)DD);
            #pragma unroll
            for (int pf = 0; pf < 2; ++pf)
                asm volatile("prefetch.global.L2 [%0];"
                             :: "l"(np + (pf * NTHREADS + tid) * 128));
        }

        // ---- epilogue 1: scale*invnorm -> bucketize -> 8-bit indices to smem ----
        {
            const float2* scl2 = (const float2*)(sb + SM_SCL);
            #pragma unroll
            for (int nt = 0; nt < 16; ++nt) {
                float2 sc = scl2[(8 * nt + 2 * t) >> 1];
                float f0 = acc[nt][0] * sc.x * inv0, f1 = acc[nt][1] * sc.y * inv0;
                float f2 = acc[nt][2] * sc.x * inv1, f3 = acc[nt][3] * sc.y * inv1;
                int i0 = 0, i1 = 0, i2 = 0, i3 = 0;
                #pragma unroll
                for (int q = 0; q < 7; ++q) {
                    i0 += (f0 > bn[q]); i1 += (f1 > bn[q]);
                    i2 += (f2 > bn[q]); i3 += (f3 > bn[q]);
                }
                *(uint16_t*)(zi + rA * 132 + 8 * nt + 2 * t)       = (uint16_t)(i0 | (i1 << 8));
                *(uint16_t*)(zi + (rA + 8) * 132 + 8 * nt + 2 * t) = (uint16_t)(i2 | (i3 << 8));
            }
        }
        __syncwarp();

        // ---- GEMM2 (hi/lo fp16, 2 MMAs per k16 step): reuse acc regs ----
        #pragma unroll
        for (int nt = 0; nt < 16; ++nt)
            #pragma unroll
            for (int p = 0; p < 4; ++p) acc[nt][p] = 0.0f;

        {
            const char* ziA = zi + rA * 132;
            const char* ziB = zi + (rA + 8) * 132;
            #pragma unroll 2
            for (int ks = 0; ks < 8; ++ks) {
                int c0 = 16 * ks + 2 * t;
                float2 is0 = *(const float2*)&isclp[c0];
                float2 is8 = *(const float2*)&isclp[c0 + 8];
                uint32_t p0 = *(const uint16_t*)(ziA + c0);
                uint32_t p1 = *(const uint16_t*)(ziB + c0);
                uint32_t p2 = *(const uint16_t*)(ziA + c0 + 8);
                uint32_t p3 = *(const uint16_t*)(ziB + c0 + 8);
                float z00 = __shfl_sync(0xffffffffu, ccv, p0 & 0xff) * is0.x;
                float z01 = __shfl_sync(0xffffffffu, ccv, p0 >> 8)   * is0.y;
                float z10 = __shfl_sync(0xffffffffu, ccv, p1 & 0xff) * is0.x;
                float z11 = __shfl_sync(0xffffffffu, ccv, p1 >> 8)   * is0.y;
                float z02 = __shfl_sync(0xffffffffu, ccv, p2 & 0xff) * is8.x;
                float z03 = __shfl_sync(0xffffffffu, ccv, p2 >> 8)   * is8.y;
                float z12 = __shfl_sync(0xffffffffu, ccv, p3 & 0xff) * is8.x;
                float z13 = __shfl_sync(0xffffffffu, ccv, p3 >> 8)   * is8.y;
                uint32_t zh[4], zl[4];
                zh[0] = h2pack(z00, z01);
                zh[1] = h2pack(z10, z11);
                zh[2] = h2pack(z02, z03);
                zh[3] = h2pack(z12, z13);
                float2 q0 = h2unpack(zh[0]), q1 = h2unpack(zh[1]);
                float2 q2 = h2unpack(zh[2]), q3 = h2unpack(zh[3]);
                zl[0] = h2pack(z00 - q0.x, z01 - q0.y);
                zl[1] = h2pack(z10 - q1.x, z11 - q1.y);
                zl[2] = h2pack(z02 - q2.x, z03 - q2.y);
                zl[3] = h2pack(z12 - q3.x, z13 - q3.y);

                uint2 cb[2][4];
                #pragma unroll
                for (int j = 0; j < 4; ++j)
                    cb[0][j] = b2q[(ks * 16 + j) * 32 + lane];
                #pragma unroll
                for (int grp = 0; grp < 4; ++grp) {
                    const int cur = grp & 1, nxt = cur ^ 1;
                    if (grp < 3) {
                        #pragma unroll
                        for (int j = 0; j < 4; ++j)
                            cb[nxt][j] = b2q[(ks * 16 + (grp + 1) * 4 + j) * 32 + lane];
                    }
                    #pragma unroll
                    for (int j = 0; j < 4; ++j) {
                        int nt = grp * 4 + j;
                        mma16(acc[nt], zh, cb[cur][j].x, cb[cur][j].y);
                        mma16(acc[nt], zl, cb[cur][j].x, cb[cur][j].y);
                    }
                }
            }
        }

        // ---- epilogue 2: x norm, store ----
        {
            float* o0 = out + (rowbase + rA) * (long)DD;
            float* o1 = o0 + 8 * DD;
            #pragma unroll
            for (int nt = 0; nt < 16; ++nt) {
                int c = 8 * nt + 2 * t;
                *(float2*)(o0 + c) = make_float2(acc[nt][0] * nrm0, acc[nt][1] * nrm0);
                *(float2*)(o1 + c) = make_float2(acc[nt][2] * nrm1, acc[nt][3] * nrm1);
            }
        }
    }
}

extern "C" void kernel_launch(void* const* d_in, const int* in_sizes, int n_in,
                              void* d_out, int out_size) {
    const float* k      = (const float*)d_in[0];
    const float* rot    = (const float*)d_in[1];
    const float* scales = (const float*)d_in[2];
    const float* cent   = (const float*)d_in[3];
    float* out = (float*)d_out;

    int nrows = in_sizes[0] / DD;
    int nblocks = nrows / (ROWS_ITER * ITERS);   // 1048576 / 1024 = 1024

    cudaFuncSetAttribute(rotadapt_mma_kernel,
                         cudaFuncAttributeMaxDynamicSharedMemorySize, SMEM_BYTES);
    rotadapt_mma_kernel<<<nblocks, NTHREADS, SMEM_BYTES>>>(k, rot, scales, cent, out);
}